// round 1
// baseline (speedup 1.0000x reference)
#include <cuda_runtime.h>
#include <cstdint>
#include <cstddef>

// Problem constants
#define BATCH 16384
#define NFEAT 512
#define NUSED 256
#define NLEAF 1024
#define NCLS  100
#define NCLSP 128   // padded class count for GEMM2 tile

// -------- device scratch (no allocations allowed) --------
__device__ int   g_sel[NUSED];                 // selected feature index per used slot
__device__ float g_x[BATCH * NUSED];           // gathered features   [B,256]   16 MB
__device__ float g_d[BATCH * NLEAF];           // d, then mu in-place [B,1024]  64 MB
__device__ float g_probs[NLEAF * NCLSP];       // softmax(pi), padded [1024,128]

// Packed f32x2 FMA (Blackwell): 2 MACs per instruction. ptxas never emits this
// from C++ — must be hand-written PTX.
__device__ __forceinline__ void ffma2(float2 &d, float2 a, float2 b) {
    asm("fma.rn.f32x2 %0, %1, %2, %0;"
        : "+l"(reinterpret_cast<unsigned long long &>(d))
        : "l"(reinterpret_cast<unsigned long long &>(a)),
          "l"(reinterpret_cast<unsigned long long &>(b)));
}

__device__ __forceinline__ float sigm(float z) {
    return 1.f / (1.f + __expf(-z));
}

// -------- prep: mask row -> feature index --------
__global__ void k_sel(const float* __restrict__ mask) {
    int j = threadIdx.x;
    if (j < NUSED) {
        const float* row = mask + j * NFEAT;
        int s = 0;
        for (int f = 0; f < NFEAT; ++f) {
            if (row[f] > 0.5f) { s = f; break; }
        }
        g_sel[j] = s;
    }
}

// -------- prep: probs = softmax(pi, axis=-1), zero-padded to 128 cols --------
__global__ void k_softmax(const float* __restrict__ pi) {
    int r = blockIdx.x * blockDim.x + threadIdx.x;
    if (r >= NLEAF) return;
    const float* p = pi + r * NCLS;
    float mx = p[0];
    for (int c = 1; c < NCLS; ++c) mx = fmaxf(mx, p[c]);
    float s = 0.f;
    for (int c = 0; c < NCLS; ++c) s += expf(p[c] - mx);
    float inv = 1.f / s;
    float* o = g_probs + r * NCLSP;
    for (int c = 0; c < NCLS; ++c)  o[c] = expf(p[c] - mx) * inv;
    for (int c = NCLS; c < NCLSP; ++c) o[c] = 0.f;
}

// -------- gather: x[b, j] = features[b, sel[j]] --------
__global__ void k_gather(const float* __restrict__ feat) {
    int i = blockIdx.x * 256 + threadIdx.x;      // 0 .. BATCH*NUSED-1
    int row = i >> 8;
    int j   = i & 255;
    g_x[i] = feat[(size_t)row * NFEAT + g_sel[j]];
}

// -------- generic register-tiled fp32(x2) GEMM --------
// C[64 x 128] tile per block, 256 threads, thread tile 8x4 (rows packed in f32x2
// pairs). SIG=true: +bias, sigmoid, store to g_d (ldc=1024).
//         SIG=false: raw, store only cols<100 to out (ldc=100).
template<bool SIG>
__global__ void __launch_bounds__(256)
k_gemm(const float* __restrict__ A, int lda,
       const float* __restrict__ B, int ldb,
       const float* __restrict__ bias,
       float* __restrict__ C, int K) {
    __shared__ float XsT[32][65];   // A tile transposed: [k][row], pad -> conflict-free transpose
    __shared__ float Ws[32][128];   // B tile: [k][col]

    const int t  = threadIdx.x;
    const int m0 = blockIdx.x * 64;
    const int n0 = blockIdx.y * 128;
    const int r0 = (t >> 5) * 8;    // 8 row-groups of 8 rows; whole warp shares rows
    const int c0 = (t & 31) * 4;    // 32 col-groups of 4 cols

    float2 acc[4][4];
    #pragma unroll
    for (int i = 0; i < 4; ++i)
        #pragma unroll
        for (int j = 0; j < 4; ++j) acc[i][j] = make_float2(0.f, 0.f);

    for (int kc = 0; kc < K; kc += 32) {
        // A tile 64x32, coalesced float4 loads, transposed into XsT
        #pragma unroll
        for (int q = 0; q < 2; ++q) {
            int idx = q * 256 + t;
            int row = idx >> 3, c4 = idx & 7;
            float4 v = *reinterpret_cast<const float4*>(
                A + (size_t)(m0 + row) * lda + kc + c4 * 4);
            XsT[c4 * 4 + 0][row] = v.x;
            XsT[c4 * 4 + 1][row] = v.y;
            XsT[c4 * 4 + 2][row] = v.z;
            XsT[c4 * 4 + 3][row] = v.w;
        }
        // B tile 32x128, coalesced float4 copy
        #pragma unroll
        for (int q = 0; q < 4; ++q) {
            int idx = q * 256 + t;
            int kr = idx >> 5, c4 = idx & 31;
            *reinterpret_cast<float4*>(&Ws[kr][c4 * 4]) =
                *reinterpret_cast<const float4*>(
                    B + (size_t)(kc + kr) * ldb + n0 + c4 * 4);
        }
        __syncthreads();

        #pragma unroll 8
        for (int kk = 0; kk < 32; ++kk) {
            float2 ap[4];
            #pragma unroll
            for (int i = 0; i < 4; ++i)
                ap[i] = make_float2(XsT[kk][r0 + 2 * i], XsT[kk][r0 + 2 * i + 1]);
            float4 bv = *reinterpret_cast<const float4*>(&Ws[kk][c0]);
            float2 bd[4] = { make_float2(bv.x, bv.x), make_float2(bv.y, bv.y),
                             make_float2(bv.z, bv.z), make_float2(bv.w, bv.w) };
            #pragma unroll
            for (int i = 0; i < 4; ++i)
                #pragma unroll
                for (int j = 0; j < 4; ++j)
                    ffma2(acc[i][j], ap[i], bd[j]);
        }
        __syncthreads();
    }

    if (SIG) {
        float4 bb = *reinterpret_cast<const float4*>(bias + n0 + c0);
        #pragma unroll
        for (int i = 0; i < 4; ++i) {
            float4 v0, v1;
            v0.x = sigm(acc[i][0].x + bb.x);
            v0.y = sigm(acc[i][1].x + bb.y);
            v0.z = sigm(acc[i][2].x + bb.z);
            v0.w = sigm(acc[i][3].x + bb.w);
            v1.x = sigm(acc[i][0].y + bb.x);
            v1.y = sigm(acc[i][1].y + bb.y);
            v1.z = sigm(acc[i][2].y + bb.z);
            v1.w = sigm(acc[i][3].y + bb.w);
            *reinterpret_cast<float4*>(
                C + (size_t)(m0 + r0 + 2 * i) * NLEAF + n0 + c0) = v0;
            *reinterpret_cast<float4*>(
                C + (size_t)(m0 + r0 + 2 * i + 1) * NLEAF + n0 + c0) = v1;
        }
    } else {
        if (c0 < NCLS) {   // c0 in {0,...,96}: all 4 cols valid; c0>=100: fully padded
            #pragma unroll
            for (int i = 0; i < 4; ++i) {
                float4 v0 = make_float4(acc[i][0].x, acc[i][1].x, acc[i][2].x, acc[i][3].x);
                float4 v1 = make_float4(acc[i][0].y, acc[i][1].y, acc[i][2].y, acc[i][3].y);
                *reinterpret_cast<float4*>(
                    C + (size_t)(m0 + r0 + 2 * i) * NCLS + c0) = v0;
                *reinterpret_cast<float4*>(
                    C + (size_t)(m0 + r0 + 2 * i + 1) * NCLS + c0) = v1;
            }
        }
    }
}

// -------- tree: mu[L] = prod_k dec(node_k, bit_k), in-place on g_d --------
// Leaf L (10 bits, MSB = level 0): node_k = 2^k + (L >> (10-k)),
// bit_k = (L >> (9-k)) & 1; factor = bit ? (1-d) : d.
__global__ void __launch_bounds__(256) k_tree() {
    __shared__ float ds[8][NLEAF];   // 32 KB
    const int t = threadIdx.x;
    const size_t base = (size_t)blockIdx.x * 8 * NLEAF;

    const float4* src = reinterpret_cast<const float4*>(g_d + base);
    float4* s4 = reinterpret_cast<float4*>(&ds[0][0]);
    #pragma unroll
    for (int q = 0; q < 8; ++q) s4[q * 256 + t] = src[q * 256 + t];
    __syncthreads();

    const int r  = t >> 5;
    const int l0 = t & 31;
    const float* dr = ds[r];
    float* outp = g_d + base + (size_t)r * NLEAF;

    for (int i = 0; i < 32; ++i) {
        int L = l0 + (i << 5);
        float m = 1.f;
        #pragma unroll
        for (int k = 0; k < 10; ++k) {
            int node = (1 << k) + (L >> (10 - k));
            float v  = dr[node];
            m *= ((L >> (9 - k)) & 1) ? (1.f - v) : v;
        }
        outp[L] = m;
    }
}

// -------- launch --------
extern "C" void kernel_launch(void* const* d_in, const int* in_sizes, int n_in,
                              void* d_out, int out_size) {
    const float* feat = (const float*)d_in[0];   // [16384,512]
    const float* mask = (const float*)d_in[1];   // [256,512]
    const float* W    = (const float*)d_in[2];   // [256,1024]
    const float* b    = (const float*)d_in[3];   // [1024]
    const float* pi   = (const float*)d_in[4];   // [1024,100]
    float* out = (float*)d_out;                  // [16384,100]
    (void)in_sizes; (void)n_in; (void)out_size;

    void *px = nullptr, *pd = nullptr, *pp = nullptr;
    cudaGetSymbolAddress(&px, g_x);
    cudaGetSymbolAddress(&pd, g_d);
    cudaGetSymbolAddress(&pp, g_probs);

    k_sel<<<1, 256>>>(mask);
    k_softmax<<<4, 256>>>(pi);
    k_gather<<<BATCH, 256>>>(feat);
    // GEMM1: d = sigmoid(x @ W + b)  -> g_d
    k_gemm<true><<<dim3(BATCH / 64, NLEAF / 128), 256>>>(
        (const float*)px, NUSED, W, NLEAF, b, (float*)pd, NUSED);
    // tree product, in place: g_d := mu
    k_tree<<<BATCH / 8, 256>>>();
    // GEMM2: out = mu @ probs (padded to 128 cols, store first 100)
    k_gemm<false><<<dim3(BATCH / 64, 1), 256>>>(
        (const float*)pd, NLEAF, (const float*)pp, NCLSP, nullptr, out, NLEAF);
}